// round 16
// baseline (speedup 1.0000x reference)
#include <cuda_runtime.h>
#include <cuda_fp16.h>
#include <math.h>

// Problem dims (fixed)
#define BI   256
#define BJ   256
#define CC   128
#define HH   4
#define CH   32
#define MROWS (BI*BJ)     // 65536

#define LOG2E 1.4426950408889634f

// ---------------- scratch (device globals; no allocation) ----------------
__device__ __half g_trif[(size_t)HH * BI * BJ];   // exp(tri) as half
__device__ __half g_xnh[(size_t)MROWS * CC];
__device__ __half g_qh[(size_t)MROWS * CC];
__device__ __half g_kh[(size_t)MROWS * CC];
__device__ __half g_vh[(size_t)MROWS * CC];
__device__ __half g_gh[(size_t)MROWS * CC];
__device__ __half g_oh[(size_t)MROWS * CC];
// pair-packed f16 weights: per matrix 4096 uint2, idx=(g*128+n)*4+j,
// val = { h2(W[16g+2j][n], W[16g+2j+1][n]), h2(W[16g+8+2j][n], W[16g+9+2j][n]) }
__device__ uint2 g_wtf[5 * 4096];

// ---------------- f16 helpers ----------------
__device__ __forceinline__ unsigned f22u(float lo, float hi) {
    __half2 h = __floats2half2_rn(lo, hi);
    return *reinterpret_cast<unsigned*>(&h);
}
__device__ __forceinline__ unsigned hh2u(__half lo, __half hi) {
    __half2 h = __halves2half2(lo, hi);
    return *reinterpret_cast<unsigned*>(&h);
}
__device__ __forceinline__ unsigned hexp2u(unsigned x) {
    unsigned r;
    asm("ex2.approx.f16x2 %0, %1;" : "=r"(r) : "r"(x));
    return r;
}
__device__ __forceinline__ unsigned hadd2u(unsigned a, unsigned b) {
    unsigned r;
    asm("add.f16x2 %0, %1, %2;" : "=r"(r) : "r"(a), "r"(b));
    return r;
}
__device__ __forceinline__ unsigned hmul2u(unsigned a, unsigned b) {
    unsigned r;
    asm("mul.f16x2 %0, %1, %2;" : "=r"(r) : "r"(a), "r"(b));
    return r;
}
__device__ __forceinline__ float2 u2f2(unsigned u) {
    __half2 h = *reinterpret_cast<__half2*>(&u);
    return __half22float2(h);
}

// fp32-accumulator f16 mma (GEMMs, AV)
__device__ __forceinline__ void mma_f16(float &d0, float &d1, float &d2, float &d3,
                                        unsigned a0, unsigned a1, unsigned a2, unsigned a3,
                                        unsigned b0, unsigned b1) {
    asm volatile(
        "mma.sync.aligned.m16n8k16.row.col.f32.f16.f16.f32 "
        "{%0,%1,%2,%3}, {%4,%5,%6,%7}, {%8,%9}, {%0,%1,%2,%3};"
        : "+f"(d0), "+f"(d1), "+f"(d2), "+f"(d3)
        : "r"(a0), "r"(a1), "r"(a2), "r"(a3), "r"(b0), "r"(b1));
}

// f16-accumulator f16 mma (QK^T scores) — d0 = half2(c0,c1) rows lr,
// d1 = half2(c0,c1) rows lr+8; matches the softmax packing directly.
__device__ __forceinline__ void mma_f16acc(unsigned &d0, unsigned &d1,
                                           unsigned a0, unsigned a1, unsigned a2, unsigned a3,
                                           unsigned b0, unsigned b1) {
    asm volatile(
        "mma.sync.aligned.m16n8k16.row.col.f16.f16.f16.f16 "
        "{%0,%1}, {%2,%3,%4,%5}, {%6,%7}, {%0,%1};"
        : "+r"(d0), "+r"(d1)
        : "r"(a0), "r"(a1), "r"(a2), "r"(a3), "r"(b0), "r"(b1));
}

// ---------------- weight pre-convert+pack: fp32 -> paired f16 -------------
__global__ void wcvt_kernel(const float* __restrict__ wq, const float* __restrict__ wk,
                            const float* __restrict__ wv, const float* __restrict__ wg,
                            const float* __restrict__ wo) {
    const float* src = (blockIdx.y == 0) ? wq : (blockIdx.y == 1) ? wk :
                       (blockIdx.y == 2) ? wv : (blockIdx.y == 3) ? wg : wo;
    int idx = blockIdx.x * 256 + threadIdx.x;   // 0..4095
    int g   = idx >> 9;
    int n   = (idx >> 2) & 127;
    int jj  = idx & 3;
    uint2 o;
    o.x = f22u(src[(16 * g + 2 * jj) * 128 + n],     src[(16 * g + 2 * jj + 1) * 128 + n]);
    o.y = f22u(src[(16 * g + 8 + 2 * jj) * 128 + n], src[(16 * g + 9 + 2 * jj) * 128 + n]);
    g_wtf[blockIdx.y * 4096 + idx] = o;
}

// ---------------- LayerNorm + trif, warp-per-row, barrier-free ------------
__global__ void __launch_bounds__(256)
ln_tri_kernel(const float* __restrict__ x,
              const float* __restrict__ w,
              const float* __restrict__ b,
              const float* __restrict__ w_tri) {
    int warp = threadIdx.x >> 5, lane = threadIdx.x & 31;
    int row = blockIdx.x * 8 + warp;
    float4 v = ((const float4*)(x + (size_t)row * CC))[lane];
    float s  = v.x + v.y + v.z + v.w;
    float sq = v.x * v.x + v.y * v.y + v.z * v.z + v.w * v.w;
    #pragma unroll
    for (int off = 16; off; off >>= 1) {
        s  += __shfl_xor_sync(0xffffffffu, s,  off);
        sq += __shfl_xor_sync(0xffffffffu, sq, off);
    }
    float mu  = s * (1.0f / CC);
    float var = sq * (1.0f / CC) - mu * mu;
    float rs  = rsqrtf(var + 1e-5f);
    float4 w4 = ((const float4*)w)[lane];
    float4 b4 = ((const float4*)b)[lane];
    float xn0 = (v.x - mu) * rs * w4.x + b4.x;
    float xn1 = (v.y - mu) * rs * w4.y + b4.y;
    float xn2 = (v.z - mu) * rs * w4.z + b4.z;
    float xn3 = (v.w - mu) * rs * w4.w + b4.w;
    uint2 xo;
    xo.x = f22u(xn0, xn1);
    xo.y = f22u(xn2, xn3);
    ((uint2*)(g_xnh + (size_t)row * CC))[lane] = xo;

    float4 wt0 = ((const float4*)w_tri)[4 * lane + 0];
    float4 wt1 = ((const float4*)w_tri)[4 * lane + 1];
    float4 wt2 = ((const float4*)w_tri)[4 * lane + 2];
    float4 wt3 = ((const float4*)w_tri)[4 * lane + 3];
    float p0 = xn0 * wt0.x + xn1 * wt1.x + xn2 * wt2.x + xn3 * wt3.x;
    float p1 = xn0 * wt0.y + xn1 * wt1.y + xn2 * wt2.y + xn3 * wt3.y;
    float p2 = xn0 * wt0.z + xn1 * wt1.z + xn2 * wt2.z + xn3 * wt3.z;
    float p3 = xn0 * wt0.w + xn1 * wt1.w + xn2 * wt2.w + xn3 * wt3.w;
    #pragma unroll
    for (int off = 16; off; off >>= 1) {
        p0 += __shfl_xor_sync(0xffffffffu, p0, off);
        p1 += __shfl_xor_sync(0xffffffffu, p1, off);
        p2 += __shfl_xor_sync(0xffffffffu, p2, off);
        p3 += __shfl_xor_sync(0xffffffffu, p3, off);
    }
    if (lane < 4) {
        float pv = (lane == 0) ? p0 : (lane == 1) ? p1 : (lane == 2) ? p2 : p3;
        g_trif[(size_t)lane * MROWS + row] = __float2half_rn(__expf(pv));
    }
}

// ---------------- f16 GEMM body -------------------------------------------
#define ASTRH 36
template<bool HALF_OUT>
__device__ __forceinline__ void gemm_body(const __half* __restrict__ A,
                                          const uint2* __restrict__ Bp,
                                          void* __restrict__ Cv,
                                          float alpha, const float* __restrict__ bias) {
    __shared__ uint2 As[64 * ASTRH];
    int tid = threadIdx.x, warp = tid >> 5, lane = tid & 31;
    int wm = warp >> 2, wn = warp & 3;
    int j = lane & 3, lr = lane >> 2;
    int m0 = blockIdx.x * 64;

    #pragma unroll
    for (int l = 0; l < 2; l++) {
        int idx = l * 256 + tid;
        int mr = idx >> 3, g = idx & 7;
        const __half* ap = A + (size_t)(m0 + mr) * 128 + g * 16;
        uint4 lo = *(const uint4*)ap;
        uint4 hi = *(const uint4*)(ap + 8);
        uint4* d = (uint4*)(As + mr * ASTRH + g * 4);
        d[0] = make_uint4(lo.x, hi.x, lo.y, hi.y);
        d[1] = make_uint4(lo.z, hi.z, lo.w, hi.w);
    }
    __syncthreads();

    float4 acc[2][4];
    #pragma unroll
    for (int mi = 0; mi < 2; mi++)
        #pragma unroll
        for (int ni = 0; ni < 4; ni++) acc[mi][ni] = make_float4(0.f, 0.f, 0.f, 0.f);

    #pragma unroll
    for (int ks = 0; ks < 8; ks++) {
        uint2 alo[2], ahi[2];
        #pragma unroll
        for (int mi = 0; mi < 2; mi++) {
            int r = wm * 32 + mi * 16 + lr;
            alo[mi] = As[r * ASTRH + ks * 4 + j];
            ahi[mi] = As[(r + 8) * ASTRH + ks * 4 + j];
        }
        const uint2* bp = Bp + ((size_t)ks * 128 + wn * 32 + lr) * 4 + j;
        #pragma unroll
        for (int ni = 0; ni < 4; ni++) {
            uint2 b = bp[ni * 32];
            #pragma unroll
            for (int mi = 0; mi < 2; mi++)
                mma_f16(acc[mi][ni].x, acc[mi][ni].y, acc[mi][ni].z, acc[mi][ni].w,
                        alo[mi].x, ahi[mi].x, alo[mi].y, ahi[mi].y, b.x, b.y);
        }
    }

    #pragma unroll
    for (int mi = 0; mi < 2; mi++) {
        int r = m0 + wm * 32 + mi * 16 + lr;
        #pragma unroll
        for (int ni = 0; ni < 4; ni++) {
            int c = wn * 32 + ni * 8 + 2 * j;
            float bx = bias ? bias[c] : 0.f;
            float by = bias ? bias[c + 1] : 0.f;
            float lx = acc[mi][ni].x * alpha + bx, ly = acc[mi][ni].y * alpha + by;
            float hx = acc[mi][ni].z * alpha + bx, hy = acc[mi][ni].w * alpha + by;
            if (HALF_OUT) {
                *(__half2*)((__half*)Cv + (size_t)r * 128 + c)       = __floats2half2_rn(lx, ly);
                *(__half2*)((__half*)Cv + (size_t)(r + 8) * 128 + c) = __floats2half2_rn(hx, hy);
            } else {
                *(float2*)((float*)Cv + (size_t)r * 128 + c)       = make_float2(lx, ly);
                *(float2*)((float*)Cv + (size_t)(r + 8) * 128 + c) = make_float2(hx, hy);
            }
        }
    }
}

__global__ void __launch_bounds__(256, 3)
gemm4_kernel(const __half* __restrict__ A, const float* __restrict__ bg) {
    int y = blockIdx.y;
    const uint2* Bp = g_wtf + (size_t)y * 4096;
    __half* C = (y == 0) ? g_qh : (y == 1) ? g_kh : (y == 2) ? g_vh : g_gh;
    float alpha = (y == 0) ? (0.17677669529663687f * LOG2E) : 1.0f;
    const float* bias = (y == 3) ? bg : nullptr;
    gemm_body<true>(A, Bp, C, alpha, bias);
}

__global__ void __launch_bounds__(256, 3)
gemm_wo_kernel(const __half* __restrict__ A, const float* __restrict__ bo,
               float* __restrict__ C) {
    gemm_body<false>(A, g_wtf + 4 * 4096, C, 1.0f, bo);
}

// ---------------- attention: merged q-groups, f16-acc QK^T ----------------
// Block = (h, i). 8 warps x 32 q-rows (two m16 tiles). One sweep over 256
// keys in 8 chunks of 32; K/V b-frags loaded once per chunk, shared by both
// q-groups. QK^T accumulates in f16 -> c-frags ARE the packed half2 scores
// (no cvt), softmax all-f16x2, P feeds AV (fp32 acc) directly.
#define KSTRA 12
__global__ void __launch_bounds__(256, 2)
attn_kernel(const float* __restrict__ mask) {
    __shared__ uint2 kp[256 * KSTRA];
    __shared__ uint2 vp[16 * 128];
    __shared__ unsigned mb2_s[128];   // half2 (col c, c+1) of LOG2E*1e9*(m-1)

    int tid = threadIdx.x;
    int warp = tid >> 5, lane = tid & 31;
    int j = lane & 3, lr = lane >> 2;
    int h  = blockIdx.x;
    int i  = blockIdx.y;

    if (tid < 128) {
        float2 m2 = *(const float2*)(mask + (size_t)i * BJ + 2 * tid);
        mb2_s[tid] = f22u((1.0e9f * LOG2E) * (m2.x - 1.0f),
                          (1.0e9f * LOG2E) * (m2.y - 1.0f));
    }

    // ---- stage K pairs ----
    #pragma unroll
    for (int l = 0; l < 2; l++) {
        int idx = l * 256 + tid;
        int key = idx >> 1, g = idx & 1;
        const __half* kg = g_kh + ((size_t)(i * BJ + key)) * 128 + h * 32 + g * 16;
        uint4 lo = *(const uint4*)kg;
        uint4 hi = *(const uint4*)(kg + 8);
        uint4* d = (uint4*)(kp + key * KSTRA + g * 4);
        d[0] = make_uint4(lo.x, hi.x, lo.y, hi.y);
        d[1] = make_uint4(lo.z, hi.z, lo.w, hi.w);
    }
    // ---- stage V pairs ----
    {
        int kg = tid >> 4, jj = (tid >> 2) & 3, dq = tid & 3;
        int rA = kg * 16 + 2 * jj;
        const __half* vb = g_vh + ((size_t)(i * BJ + rA)) * 128 + h * 32 + dq * 8;
        uint4 a4 = *(const uint4*)vb;
        uint4 b4 = *(const uint4*)(vb + 128);
        uint4 c4 = *(const uint4*)(vb + 8 * 128);
        uint4 d4 = *(const uint4*)(vb + 9 * 128);
        const __half* ah = (const __half*)&a4;
        const __half* bh = (const __half*)&b4;
        const __half* chh = (const __half*)&c4;
        const __half* dh = (const __half*)&d4;
        #pragma unroll
        for (int d = 0; d < 8; d++) {
            uint2 o;
            o.x = hh2u(ah[d], bh[d]);
            o.y = hh2u(chh[d], dh[d]);
            vp[(kg * 32 + dq * 8 + d) * 4 + jj] = o;
        }
    }
    __syncthreads();   // only barrier

    // ---- both q-groups resident: rows qg*128 + warp*16 + lr (+8) ----
    unsigned aq[2][2][4];
    const __half2 *tlo[2], *thi[2];
    #pragma unroll
    for (int qg = 0; qg < 2; qg++) {
        int qrow = qg * 128 + warp * 16 + lr;
        const __half* qp  = g_qh + ((size_t)(i * BJ + qrow)) * 128 + h * 32;
        const __half* qp8 = qp + 8 * 128;
        #pragma unroll
        for (int g = 0; g < 2; g++) {
            aq[qg][g][0] = *(const unsigned*)(qp  + (8 * g + j) * 2);
            aq[qg][g][1] = *(const unsigned*)(qp8 + (8 * g + j) * 2);
            aq[qg][g][2] = *(const unsigned*)(qp  + (8 * g + 4 + j) * 2);
            aq[qg][g][3] = *(const unsigned*)(qp8 + (8 * g + 4 + j) * 2);
        }
        tlo[qg] = (const __half2*)(g_trif + (size_t)h * MROWS) + qrow * 128;
        thi[qg] = tlo[qg] + 8 * 128;
    }

    float4 o[2][4];
    #pragma unroll
    for (int qg = 0; qg < 2; qg++)
        #pragma unroll
        for (int t = 0; t < 4; t++) o[qg][t] = make_float4(0.f, 0.f, 0.f, 0.f);
    float lsum[2][2] = {{0.f, 0.f}, {0.f, 0.f}};

    // ---- single sweep: 8 chunks of 32 keys ----
    #pragma unroll 2
    for (int ch = 0; ch < 8; ch++) {
        // K b-frags: loaded ONCE, used by both q-groups
        uint2 kb[4][2];
        #pragma unroll
        for (int nt = 0; nt < 4; nt++) {
            int n = ch * 32 + nt * 8 + lr;
            kb[nt][0] = kp[n * KSTRA + j];
            kb[nt][1] = kp[n * KSTRA + 4 + j];
        }
        // V b-frags issued early (overlap LDS latency with softmax MUFU work)
        uint2 vbf[2][4];
        #pragma unroll
        for (int kg2 = 0; kg2 < 2; kg2++) {
            const uint2* vb = vp + (ch * 2 + kg2) * 128 + j;
            #pragma unroll
            for (int nt2 = 0; nt2 < 4; nt2++) vbf[kg2][nt2] = vb[(nt2 * 8 + lr) * 4];
        }
        unsigned p[2][4][2];
        #pragma unroll
        for (int qg = 0; qg < 2; qg++) {
            // f16-acc QK^T: c-frags are packed half2 scores
            unsigned acc2[4][2];
            #pragma unroll
            for (int nt = 0; nt < 4; nt++) { acc2[nt][0] = 0u; acc2[nt][1] = 0u; }
            #pragma unroll
            for (int ks = 0; ks < 2; ks++)
                #pragma unroll
                for (int nt = 0; nt < 4; nt++)
                    mma_f16acc(acc2[nt][0], acc2[nt][1],
                               aq[qg][ks][0], aq[qg][ks][1], aq[qg][ks][2], aq[qg][ks][3],
                               kb[nt][ks].x, kb[nt][ks].y);
            unsigned sum0 = 0u, sum1 = 0u;
            #pragma unroll
            for (int nt = 0; nt < 4; nt++) {
                int c2 = ch * 16 + nt * 4 + j;
                unsigned mb2 = mb2_s[c2];
                unsigned pl = hexp2u(hadd2u(acc2[nt][0], mb2));
                unsigned ph = hexp2u(hadd2u(acc2[nt][1], mb2));
                pl = hmul2u(pl, *(const unsigned*)(tlo[qg] + c2));
                ph = hmul2u(ph, *(const unsigned*)(thi[qg] + c2));
                p[qg][nt][0] = pl; p[qg][nt][1] = ph;
                sum0 = hadd2u(sum0, pl);
                sum1 = hadd2u(sum1, ph);
            }
            float2 f0 = u2f2(sum0); lsum[qg][0] += f0.x + f0.y;
            float2 f1 = u2f2(sum1); lsum[qg][1] += f1.x + f1.y;
        }
        // AV: prefetched V b-frags, both q-groups
        #pragma unroll
        for (int kg2 = 0; kg2 < 2; kg2++) {
            #pragma unroll
            for (int nt2 = 0; nt2 < 4; nt2++) {
                uint2 b = vbf[kg2][nt2];
                #pragma unroll
                for (int qg = 0; qg < 2; qg++)
                    mma_f16(o[qg][nt2].x, o[qg][nt2].y, o[qg][nt2].z, o[qg][nt2].w,
                            p[qg][2 * kg2][0], p[qg][2 * kg2][1],
                            p[qg][2 * kg2 + 1][0], p[qg][2 * kg2 + 1][1],
                            b.x, b.y);
            }
        }
    }

    // ---- epilogue per q-group ----
    #pragma unroll
    for (int qg = 0; qg < 2; qg++) {
        float l0 = lsum[qg][0], l1 = lsum[qg][1];
        l0 += __shfl_xor_sync(0xffffffffu, l0, 1);
        l0 += __shfl_xor_sync(0xffffffffu, l0, 2);
        l1 += __shfl_xor_sync(0xffffffffu, l1, 1);
        l1 += __shfl_xor_sync(0xffffffffu, l1, 2);
        float inv0 = __fdividef(1.0f, l0);
        float inv1 = __fdividef(1.0f, l1);
        int qrow = qg * 128 + warp * 16 + lr;
        #pragma unroll
        for (int rr = 0; rr < 2; rr++) {
            int jq = qrow + rr * 8;
            size_t base = ((size_t)(i * BJ + jq)) * 128 + h * 32;
            #pragma unroll
            for (int nt2 = 0; nt2 < 4; nt2++) {
                int d = nt2 * 8 + 2 * j;
                float2 gv = __half22float2(*(const __half2*)(g_gh + base + d));
                float vx = (rr ? o[qg][nt2].z * inv1 : o[qg][nt2].x * inv0);
                float vy = (rr ? o[qg][nt2].w * inv1 : o[qg][nt2].y * inv0);
                float ox = __fdividef(vx, 1.0f + __expf(-gv.x));
                float oy = __fdividef(vy, 1.0f + __expf(-gv.y));
                *(__half2*)(g_oh + base + d) = __floats2half2_rn(ox, oy);
            }
        }
    }
}

// ---------------- launch ----------------
extern "C" void kernel_launch(void* const* d_in, const int* in_sizes, int n_in,
                              void* d_out, int out_size) {
    const float* x     = (const float*)d_in[0];
    const float* mask  = (const float*)d_in[1];
    const float* ln_w  = (const float*)d_in[3];
    const float* ln_b  = (const float*)d_in[4];
    const float* w_tri = (const float*)d_in[5];
    const float* wq    = (const float*)d_in[6];
    const float* wk    = (const float*)d_in[7];
    const float* wv    = (const float*)d_in[8];
    const float* wg    = (const float*)d_in[9];
    const float* bg    = (const float*)d_in[10];
    const float* wo    = (const float*)d_in[11];
    const float* bo    = (const float*)d_in[12];
    float* out = (float*)d_out;

    __half *xnh_p, *oh_p;
    cudaGetSymbolAddress((void**)&xnh_p, g_xnh);
    cudaGetSymbolAddress((void**)&oh_p, g_oh);

    dim3 wgrid(16, 5);
    wcvt_kernel<<<wgrid, 256>>>(wq, wk, wv, wg, wo);
    ln_tri_kernel<<<MROWS / 8, 256>>>(x, ln_w, ln_b, w_tri);

    dim3 ggrid(MROWS / 64, 4);
    gemm4_kernel<<<ggrid, 256>>>(xnh_p, bg);

    dim3 agrid(HH, BI);
    attn_kernel<<<agrid, 256>>>(mask);

    gemm_wo_kernel<<<MROWS / 64, 256>>>(oh_p, bo, out);
}